// round 2
// baseline (speedup 1.0000x reference)
#include <cuda_runtime.h>

#define NN 50000
#define NE 600000
#define HID 128
#define NUM_L 4
#define NG 256
#define BN_EPS 1e-5f

// ---------------- device scratch (static, no allocation) ----------------
__device__ int      g_cnt[NN];
__device__ int      g_rowptr[NN + 1];
__device__ unsigned g_edges[NE];          // packed src(16b) | a0(3b)<<16 | a1<<19 | a2<<22
__device__ float    g_h[NN * HID];
__device__ float    g_z[NN * HID];
__device__ float    g_sums[NG * HID];
__device__ int      g_gcnt[NG];

// ---------------- small setup kernels ----------------
__global__ void zero_kernel() {
    int i = blockIdx.x * blockDim.x + threadIdx.x;
    if (i < NN) g_cnt[i] = 0;
    if (i < NG * HID) g_sums[i] = 0.f;
    if (i < NG) g_gcnt[i] = 0;
}

__global__ void hist_kernel(const int* __restrict__ ei) {
    int e = blockIdx.x * blockDim.x + threadIdx.x;
    if (e < NE) atomicAdd(&g_cnt[ei[NE + e]], 1);
}

__global__ void scan_kernel() {
    __shared__ int ss[1024];
    const int t = threadIdx.x;
    const int CH = 49;                      // 1024*49 = 50176 >= NN
    int base = t * CH;
    int s = 0;
    for (int i = 0; i < CH; i++) {
        int idx = base + i;
        if (idx < NN) s += g_cnt[idx];
    }
    ss[t] = s;
    __syncthreads();
    for (int off = 1; off < 1024; off <<= 1) {
        int v = (t >= off) ? ss[t - off] : 0;
        __syncthreads();
        ss[t] += v;
        __syncthreads();
    }
    int run = ss[t] - s;                    // exclusive prefix for this chunk
    for (int i = 0; i < CH; i++) {
        int idx = base + i;
        if (idx < NN) {
            int cv = g_cnt[idx];
            g_rowptr[idx] = run;
            run += cv;
            g_cnt[idx] = 0;                 // reset for scatter pass
        }
    }
    if (t == 0) g_rowptr[NN] = NE;
}

__global__ void scatter_kernel(const int* __restrict__ ei, const int* __restrict__ ea) {
    int e = blockIdx.x * blockDim.x + threadIdx.x;
    if (e >= NE) return;
    int d = ei[NE + e];
    int srcv = ei[e];
    int a0 = ea[e * 3 + 0], a1 = ea[e * 3 + 1], a2 = ea[e * 3 + 2];
    unsigned u = (unsigned)srcv | ((unsigned)a0 << 16) | ((unsigned)a1 << 19) | ((unsigned)a2 << 22);
    int pos = atomicAdd(&g_cnt[d], 1);
    g_edges[g_rowptr[d] + pos] = u;
}

// ---------------- node embedding: h[n] = sum_f atom_emb[f][x[n,f]] ----------------
__global__ void embed_kernel(const int* __restrict__ x, const float* __restrict__ atom_emb) {
    int wid = (blockIdx.x * blockDim.x + threadIdx.x) >> 5;
    if (wid >= NN) return;
    int lane = threadIdx.x & 31;
    const int* xi = x + wid * 9;
    const float4* A = (const float4*)atom_emb;
    float4 acc = make_float4(0.f, 0.f, 0.f, 0.f);
#pragma unroll
    for (int f = 0; f < 9; f++) {
        int v = __ldg(&xi[f]);
        float4 tv = __ldg(&A[(f * 64 + v) * 32 + lane]);
        acc.x += tv.x; acc.y += tv.y; acc.z += tv.z; acc.w += tv.w;
    }
    ((float4*)g_h)[wid * 32 + lane] = acc;
}

// ---------------- per-layer edge aggregation: z[n] = h[n] + sum relu(h[src]+e) ----------------
__global__ void agg_kernel(const float* __restrict__ bond) {
    int wid = (blockIdx.x * blockDim.x + threadIdx.x) >> 5;
    if (wid >= NN) return;
    int lane = threadIdx.x & 31;
    const float4* H = (const float4*)g_h;
    const float4* B = (const float4*)bond;
    float4 acc = H[wid * 32 + lane];
    int s = g_rowptr[wid], e = g_rowptr[wid + 1];
    for (int i = s; i < e; i++) {
        unsigned u = __ldg(&g_edges[i]);
        int src = u & 0xFFFF;
        float4 hv = H[src * 32 + lane];
        float4 e0 = __ldg(&B[(((u >> 16) & 7)) * 32 + lane]);
        float4 e1 = __ldg(&B[(8 + ((u >> 19) & 7)) * 32 + lane]);
        float4 e2 = __ldg(&B[(16 + ((u >> 22) & 7)) * 32 + lane]);
        float m;
        m = hv.x + e0.x + e1.x + e2.x; acc.x += fmaxf(m, 0.f);
        m = hv.y + e0.y + e1.y + e2.y; acc.y += fmaxf(m, 0.f);
        m = hv.z + e0.z + e1.z + e2.z; acc.z += fmaxf(m, 0.f);
        m = hv.w + e0.w + e1.w + e2.w; acc.w += fmaxf(m, 0.f);
    }
    ((float4*)g_z)[wid * 32 + lane] = acc;
}

// ---------------- fused MLP + BN + residual: h += relu(BN(relu(z@W1+b1)@W2+b2)) ----------------
// BM=64 rows/block, 256 threads, 8 warps x 8 rows, lane owns 4 cols.
// smem: Ws 64KB (full 128x128 weight) + Zs 32KB (64x128 tile, reused for t).
__global__ __launch_bounds__(256, 2) void mlp_kernel(
    const float* __restrict__ W1, const float* __restrict__ b1,
    const float* __restrict__ W2, const float* __restrict__ b2,
    const float* __restrict__ gam, const float* __restrict__ bet,
    const float* __restrict__ mean, const float* __restrict__ var) {
    extern __shared__ float sm[];
    float* Ws = sm;                 // 128*128
    float* Zs = sm + 128 * 128;     // 64*128
    const int tid = threadIdx.x, lane = tid & 31, wp = tid >> 5;
    const int rbase = blockIdx.x * 64;
    const int col = lane * 4;
    const int rloc = wp * 8;

    // stage W1
    {
        const float4* src = (const float4*)W1;
        float4* dst = (float4*)Ws;
#pragma unroll
        for (int i = 0; i < 16; i++) dst[tid + i * 256] = src[tid + i * 256];
    }
    // stage z tile (row-major [64][128])
    {
        const float4* zg = (const float4*)g_z;
        float4* dst = (float4*)Zs;
#pragma unroll
        for (int i = 0; i < 8; i++) {
            int idx = tid + i * 256;            // 0..2047
            int r = idx >> 5;
            int gr = rbase + r;
            dst[idx] = (gr < NN) ? zg[gr * 32 + (idx & 31)] : make_float4(0.f, 0.f, 0.f, 0.f);
        }
    }
    __syncthreads();

    float acc[8][4];
#pragma unroll
    for (int r = 0; r < 8; r++)
#pragma unroll
        for (int c = 0; c < 4; c++) acc[r][c] = 0.f;

    // GEMM1: t = relu(z @ W1 + b1)
#pragma unroll 4
    for (int k4 = 0; k4 < 32; k4++) {
        float4 w0 = *(const float4*)&Ws[(k4 * 4 + 0) * 128 + col];
        float4 w1 = *(const float4*)&Ws[(k4 * 4 + 1) * 128 + col];
        float4 w2 = *(const float4*)&Ws[(k4 * 4 + 2) * 128 + col];
        float4 w3 = *(const float4*)&Ws[(k4 * 4 + 3) * 128 + col];
#pragma unroll
        for (int r = 0; r < 8; r++) {
            float4 zv = *(const float4*)&Zs[(rloc + r) * 128 + k4 * 4];
            acc[r][0] = fmaf(zv.x, w0.x, fmaf(zv.y, w1.x, fmaf(zv.z, w2.x, fmaf(zv.w, w3.x, acc[r][0]))));
            acc[r][1] = fmaf(zv.x, w0.y, fmaf(zv.y, w1.y, fmaf(zv.z, w2.y, fmaf(zv.w, w3.y, acc[r][1]))));
            acc[r][2] = fmaf(zv.x, w0.z, fmaf(zv.y, w1.z, fmaf(zv.z, w2.z, fmaf(zv.w, w3.z, acc[r][2]))));
            acc[r][3] = fmaf(zv.x, w0.w, fmaf(zv.y, w1.w, fmaf(zv.z, w2.w, fmaf(zv.w, w3.w, acc[r][3]))));
        }
    }

    float4 b1v = *(const float4*)&b1[col];
    __syncthreads();   // everyone done reading Zs/Ws

    // write t into Zs, reset acc
#pragma unroll
    for (int r = 0; r < 8; r++) {
        float4 tv;
        tv.x = fmaxf(acc[r][0] + b1v.x, 0.f);
        tv.y = fmaxf(acc[r][1] + b1v.y, 0.f);
        tv.z = fmaxf(acc[r][2] + b1v.z, 0.f);
        tv.w = fmaxf(acc[r][3] + b1v.w, 0.f);
        *(float4*)&Zs[(rloc + r) * 128 + col] = tv;
        acc[r][0] = acc[r][1] = acc[r][2] = acc[r][3] = 0.f;
    }
    // stage W2
    {
        const float4* src = (const float4*)W2;
        float4* dst = (float4*)Ws;
#pragma unroll
        for (int i = 0; i < 16; i++) dst[tid + i * 256] = src[tid + i * 256];
    }
    __syncthreads();

    // GEMM2: u = t @ W2 + b2
#pragma unroll 4
    for (int k4 = 0; k4 < 32; k4++) {
        float4 w0 = *(const float4*)&Ws[(k4 * 4 + 0) * 128 + col];
        float4 w1 = *(const float4*)&Ws[(k4 * 4 + 1) * 128 + col];
        float4 w2 = *(const float4*)&Ws[(k4 * 4 + 2) * 128 + col];
        float4 w3 = *(const float4*)&Ws[(k4 * 4 + 3) * 128 + col];
#pragma unroll
        for (int r = 0; r < 8; r++) {
            float4 zv = *(const float4*)&Zs[(rloc + r) * 128 + k4 * 4];
            acc[r][0] = fmaf(zv.x, w0.x, fmaf(zv.y, w1.x, fmaf(zv.z, w2.x, fmaf(zv.w, w3.x, acc[r][0]))));
            acc[r][1] = fmaf(zv.x, w0.y, fmaf(zv.y, w1.y, fmaf(zv.z, w2.y, fmaf(zv.w, w3.y, acc[r][1]))));
            acc[r][2] = fmaf(zv.x, w0.z, fmaf(zv.y, w1.z, fmaf(zv.z, w2.z, fmaf(zv.w, w3.z, acc[r][2]))));
            acc[r][3] = fmaf(zv.x, w0.w, fmaf(zv.y, w1.w, fmaf(zv.z, w2.w, fmaf(zv.w, w3.w, acc[r][3]))));
        }
    }

    // epilogue: BN (folded) + residual relu
    float4 b2v = *(const float4*)&b2[col];
    float4 gv = *(const float4*)&gam[col];
    float4 bv = *(const float4*)&bet[col];
    float4 mv = *(const float4*)&mean[col];
    float4 vv = *(const float4*)&var[col];
    float s0 = gv.x * rsqrtf(vv.x + BN_EPS);
    float s1 = gv.y * rsqrtf(vv.y + BN_EPS);
    float s2 = gv.z * rsqrtf(vv.z + BN_EPS);
    float s3 = gv.w * rsqrtf(vv.w + BN_EPS);
#pragma unroll
    for (int r = 0; r < 8; r++) {
        int gr = rbase + rloc + r;
        if (gr < NN) {
            float4 hv = *(float4*)&g_h[gr * 128 + col];
            float y;
            y = (acc[r][0] + b2v.x - mv.x) * s0 + bv.x; hv.x += fmaxf(y, 0.f);
            y = (acc[r][1] + b2v.y - mv.y) * s1 + bv.y; hv.y += fmaxf(y, 0.f);
            y = (acc[r][2] + b2v.z - mv.z) * s2 + bv.z; hv.z += fmaxf(y, 0.f);
            y = (acc[r][3] + b2v.w - mv.w) * s3 + bv.w; hv.w += fmaxf(y, 0.f);
            *(float4*)&g_h[gr * 128 + col] = hv;
        }
    }
}

// ---------------- pooling ----------------
__global__ void pool_kernel(const int* __restrict__ batch) {
    int wid = (blockIdx.x * blockDim.x + threadIdx.x) >> 5;
    if (wid >= NN) return;
    int lane = threadIdx.x & 31;
    int g = __ldg(&batch[wid]);
    float4 hv = ((const float4*)g_h)[wid * 32 + lane];
    float* sp = &g_sums[g * HID + lane * 4];
    atomicAdd(sp + 0, hv.x);
    atomicAdd(sp + 1, hv.y);
    atomicAdd(sp + 2, hv.z);
    atomicAdd(sp + 3, hv.w);
    if (lane == 0) atomicAdd(&g_gcnt[g], 1);
}

__global__ void final_kernel(const float* __restrict__ mlp_w, const float* __restrict__ mlp_b,
                             float* __restrict__ out) {
    int g = (blockIdx.x * blockDim.x + threadIdx.x) >> 5;
    if (g >= NG) return;
    int lane = threadIdx.x & 31;
    float cnt = fmaxf((float)g_gcnt[g], 1.f);
    float4 sv = ((const float4*)g_sums)[g * 32 + lane];
    float4 wv = ((const float4*)mlp_w)[lane];
    float p = (sv.x * wv.x + sv.y * wv.y + sv.z * wv.z + sv.w * wv.w) / cnt;
#pragma unroll
    for (int off = 16; off; off >>= 1) p += __shfl_xor_sync(0xFFFFFFFFu, p, off);
    if (lane == 0) out[g] = p + __ldg(&mlp_b[0]);
}

// ---------------- launcher ----------------
extern "C" void kernel_launch(void* const* d_in, const int* in_sizes, int n_in,
                              void* d_out, int out_size) {
    const int*   x        = (const int*)d_in[0];
    const int*   ei       = (const int*)d_in[1];
    const int*   ea       = (const int*)d_in[2];
    const int*   batch    = (const int*)d_in[3];
    const float* atom_emb = (const float*)d_in[4];
    const float* bond_emb = (const float*)d_in[5];
    const float* l1w      = (const float*)d_in[6];
    const float* l1b      = (const float*)d_in[7];
    const float* l2w      = (const float*)d_in[8];
    const float* l2b      = (const float*)d_in[9];
    const float* gam      = (const float*)d_in[10];
    const float* bet      = (const float*)d_in[11];
    const float* bnm      = (const float*)d_in[12];
    const float* bnv      = (const float*)d_in[13];
    const float* mlw      = (const float*)d_in[14];
    const float* mlb      = (const float*)d_in[15];
    float* out = (float*)d_out;

    const int SMEM = (128 * 128 + 64 * 128) * 4;  // 96KB
    cudaFuncSetAttribute(mlp_kernel, cudaFuncAttributeMaxDynamicSharedMemorySize, SMEM);

    zero_kernel<<<(NN + 255) / 256, 256>>>();
    hist_kernel<<<(NE + 255) / 256, 256>>>(ei);
    scan_kernel<<<1, 1024>>>();
    scatter_kernel<<<(NE + 255) / 256, 256>>>(ei, ea);
    embed_kernel<<<NN / 8, 256>>>(x, atom_emb);

    for (int l = 0; l < NUM_L; l++) {
        agg_kernel<<<NN / 8, 256>>>(bond_emb);
        mlp_kernel<<<(NN + 63) / 64, 256, SMEM>>>(
            l1w + l * HID * HID, l1b + l * HID,
            l2w + l * HID * HID, l2b + l * HID,
            gam + l * HID, bet + l * HID, bnm + l * HID, bnv + l * HID);
    }

    pool_kernel<<<NN / 8, 256>>>(batch);
    final_kernel<<<NG / 8, 256>>>(mlw, mlb, out);
}

// round 5
// speedup vs baseline: 1.2782x; 1.2782x over previous
#include <cuda_runtime.h>
#include <cstdint>

#define NN 50000
#define NE 600000
#define HID 128
#define NUM_L 4
#define NG 256
#define BN_EPS 1e-5f
#define NTILES ((NN + 127) / 128)
#define PITCH 136   // floats per smem row: conflict-free 64-bit fragment loads

__device__ int      g_cnt[NN];
__device__ int      g_rowptr[NN + 1];
__device__ unsigned g_edges[NE];
__device__ float    g_h[NN * HID];
__device__ float    g_z[NN * HID];
__device__ float    g_sums[NG * HID];
__device__ int      g_gcnt[NG];
__device__ float    g_wt[8 * HID * HID];   // [m][n][k_perm]: m<4 -> W1^T layer m, m>=4 -> W2^T

__device__ __forceinline__ uint32_t f2tf32(float x) {
    uint32_t u; asm("cvt.rna.tf32.f32 %0, %1;" : "=r"(u) : "f"(x)); return u;
}
__device__ __forceinline__ void mma_tf32(float* c, const uint32_t* a, const uint32_t* b) {
    asm volatile(
        "mma.sync.aligned.m16n8k8.row.col.f32.tf32.tf32.f32 "
        "{%0,%1,%2,%3}, {%4,%5,%6,%7}, {%8,%9}, {%0,%1,%2,%3};"
        : "+f"(c[0]), "+f"(c[1]), "+f"(c[2]), "+f"(c[3])
        : "r"(a[0]), "r"(a[1]), "r"(a[2]), "r"(a[3]), "r"(b[0]), "r"(b[1]));
}
// within-8 column permutation: c -> (c&3)*2 + (c>>2)
__device__ __host__ __forceinline__ int kperm(int c) { return ((c & 3) << 1) | (c >> 2); }

// ---------------- setup kernels ----------------
__global__ void zero_kernel() {
    int i = blockIdx.x * blockDim.x + threadIdx.x;
    if (i < NN) g_cnt[i] = 0;
    if (i < NG * HID) g_sums[i] = 0.f;
    if (i < NG) g_gcnt[i] = 0;
}

__global__ void hist_kernel(const int* __restrict__ ei) {
    int e = blockIdx.x * blockDim.x + threadIdx.x;
    if (e < NE) atomicAdd(&g_cnt[ei[NE + e]], 1);
}

__global__ void scan_kernel() {
    __shared__ int ss[1024];
    const int t = threadIdx.x;
    const int CH = 49;
    int base = t * CH;
    int s = 0;
    for (int i = 0; i < CH; i++) {
        int idx = base + i;
        if (idx < NN) s += g_cnt[idx];
    }
    ss[t] = s;
    __syncthreads();
    for (int off = 1; off < 1024; off <<= 1) {
        int v = (t >= off) ? ss[t - off] : 0;
        __syncthreads();
        ss[t] += v;
        __syncthreads();
    }
    int run = ss[t] - s;
    for (int i = 0; i < CH; i++) {
        int idx = base + i;
        if (idx < NN) {
            int cv = g_cnt[idx];
            g_rowptr[idx] = run;
            run += cv;
            g_cnt[idx] = 0;
        }
    }
    if (t == 0) g_rowptr[NN] = NE;
}

__global__ void scatter_kernel(const int* __restrict__ ei, const int* __restrict__ ea) {
    int e = blockIdx.x * blockDim.x + threadIdx.x;
    if (e >= NE) return;
    int d = ei[NE + e];
    int srcv = ei[e];
    int a0 = ea[e * 3 + 0], a1 = ea[e * 3 + 1], a2 = ea[e * 3 + 2];
    unsigned u = (unsigned)srcv | ((unsigned)a0 << 16) | ((unsigned)a1 << 19) | ((unsigned)a2 << 22);
    int pos = atomicAdd(&g_cnt[d], 1);
    g_edges[g_rowptr[d] + pos] = u;
}

// transpose + tf32-convert + k-permute: g_wt[m][n][kp] = tf32(W[k][n])
__global__ void wtrans_kernel(const float* __restrict__ l1w, const float* __restrict__ l2w) {
    __shared__ float ts[32][33];
    int m = blockIdx.z;
    const float* src = (m < 4) ? (l1w + m * HID * HID) : (l2w + (m - 4) * HID * HID);
    int bx = blockIdx.x * 32, by = blockIdx.y * 32;
    for (int i = threadIdx.y; i < 32; i += 8)
        ts[i][threadIdx.x] = src[(by + i) * HID + bx + threadIdx.x];
    __syncthreads();
    for (int i = threadIdx.y; i < 32; i += 8) {
        int k = by + threadIdx.x;
        int kp = (k & ~7) | kperm(k & 7);
        g_wt[m * HID * HID + (bx + i) * HID + kp] =
            __uint_as_float(f2tf32(ts[threadIdx.x][i]));
    }
}

// ---------------- node embedding ----------------
__global__ void embed_kernel(const int* __restrict__ x, const float* __restrict__ atom_emb) {
    int wid = (blockIdx.x * blockDim.x + threadIdx.x) >> 5;
    if (wid >= NN) return;
    int lane = threadIdx.x & 31;
    const int* xi = x + wid * 9;
    const float4* A = (const float4*)atom_emb;
    float4 acc = make_float4(0.f, 0.f, 0.f, 0.f);
#pragma unroll
    for (int f = 0; f < 9; f++) {
        int v = __ldg(&xi[f]);
        float4 tv = __ldg(&A[(f * 64 + v) * 32 + lane]);
        acc.x += tv.x; acc.y += tv.y; acc.z += tv.z; acc.w += tv.w;
    }
    ((float4*)g_h)[wid * 32 + lane] = acc;
}

// ---------------- edge aggregation ----------------
__global__ void agg_kernel(const float* __restrict__ bond) {
    int wid = (blockIdx.x * blockDim.x + threadIdx.x) >> 5;
    if (wid >= NN) return;
    int lane = threadIdx.x & 31;
    const float4* H = (const float4*)g_h;
    const float4* B = (const float4*)bond;
    float4 acc = H[wid * 32 + lane];
    int s = g_rowptr[wid], e = g_rowptr[wid + 1];
    for (int i = s; i < e; i++) {
        unsigned u = __ldg(&g_edges[i]);
        int src = u & 0xFFFF;
        float4 hv = H[src * 32 + lane];
        float4 e0 = __ldg(&B[(((u >> 16) & 7)) * 32 + lane]);
        float4 e1 = __ldg(&B[(8 + ((u >> 19) & 7)) * 32 + lane]);
        float4 e2 = __ldg(&B[(16 + ((u >> 22) & 7)) * 32 + lane]);
        float m;
        m = hv.x + e0.x + e1.x + e2.x; acc.x += fmaxf(m, 0.f);
        m = hv.y + e0.y + e1.y + e2.y; acc.y += fmaxf(m, 0.f);
        m = hv.z + e0.z + e1.z + e2.z; acc.z += fmaxf(m, 0.f);
        m = hv.w + e0.w + e1.w + e2.w; acc.w += fmaxf(m, 0.f);
    }
    ((float4*)g_z)[wid * 32 + lane] = acc;
}

// ---------------- mma.sync tf32 fused MLP + BN + residual ----------------
// smem: [0,2048) ctrl (sb1 @0, sc0 @512, sc1 @1024); Zs @2048 [128][136]; Ws after [128][136]
#define ZS_OFF 2048
#define WS_OFF (2048 + 128 * PITCH * 4)
#define SMEM_MMA (2048 + 2 * 128 * PITCH * 4)

__global__ __launch_bounds__(256, 1)
void mlp_mma_kernel(int layer,
                    const float* __restrict__ b1, const float* __restrict__ b2,
                    const float* __restrict__ gam, const float* __restrict__ bet,
                    const float* __restrict__ mean, const float* __restrict__ var) {
    extern __shared__ char smem[];
    float* sb1 = (float*)smem;
    float* sc0 = (float*)(smem + 512);
    float* sc1 = (float*)(smem + 1024);
    float* Zs = (float*)(smem + ZS_OFF);
    float* Ws = (float*)(smem + WS_OFF);

    const int tid = threadIdx.x, lane = tid & 31, wid = tid >> 5;
    const int gid = lane >> 2, tig = lane & 3;
    const int warp_m = wid & 3, warp_n = wid >> 2;
    const int rbase = blockIdx.x * 128;
    const float* WT1 = g_wt + layer * HID * HID;
    const float* WT2 = g_wt + (4 + layer) * HID * HID;
    const int p0 = kperm(2 * tig);        // permuted pos of col 2*tig within 8-group
    const int p1 = kperm(2 * tig + 1);

    if (tid < HID) {
        float s = __ldg(&gam[tid]) * rsqrtf(__ldg(&var[tid]) + BN_EPS);
        sb1[tid] = __ldg(&b1[tid]);
        sc0[tid] = s;
        sc1[tid] = (__ldg(&b2[tid]) - __ldg(&mean[tid])) * s + __ldg(&bet[tid]);
    }

    // stage Z: tf32-cvt + k-permute; thread -> row tid/2, 64 cols
    {
        const int zr = tid >> 1, cb = (tid & 1) * 16;   // float4 base within row
        const float4* zrow = (const float4*)g_z + (size_t)(rbase + zr) * 32;
        bool ok = (rbase + zr) < NN;
#pragma unroll
        for (int g8 = 0; g8 < 8; g8++) {
            float4 lo = ok ? __ldg(&zrow[cb + g8 * 2 + 0]) : make_float4(0, 0, 0, 0);
            float4 hi = ok ? __ldg(&zrow[cb + g8 * 2 + 1]) : make_float4(0, 0, 0, 0);
            uint4 o1, o2;
            o1.x = f2tf32(lo.x); o1.y = f2tf32(hi.x); o1.z = f2tf32(lo.y); o1.w = f2tf32(hi.y);
            o2.x = f2tf32(lo.z); o2.y = f2tf32(hi.z); o2.z = f2tf32(lo.w); o2.w = f2tf32(hi.w);
            float* dst = &Zs[zr * PITCH + (tid & 1) * 64 + g8 * 8];
            *(uint4*)(dst + 0) = o1;
            *(uint4*)(dst + 4) = o2;
        }
    }
    // stage W1^T (already tf32 + permuted): plain copy
    {
        const uint4* wg = (const uint4*)WT1;
#pragma unroll
        for (int i = 0; i < 16; i++) {
            int idx = i * 256 + tid;
            int row = idx >> 5, c4 = idx & 31;
            *(uint4*)&Ws[row * PITCH + c4 * 4] = __ldg(&wg[idx]);
        }
    }
    __syncthreads();

    float c[2][8][4];
#pragma unroll
    for (int mt = 0; mt < 2; mt++)
#pragma unroll
        for (int nt = 0; nt < 8; nt++)
#pragma unroll
            for (int i = 0; i < 4; i++) c[mt][nt][i] = 0.f;

    // GEMM1
#pragma unroll
    for (int ks = 0; ks < 16; ks++) {
        uint32_t a[2][4], b[8][2];
#pragma unroll
        for (int mt = 0; mt < 2; mt++) {
            int ra = warp_m * 32 + mt * 16 + gid;
            uint2 v0 = *(const uint2*)&Zs[ra * PITCH + ks * 8 + 2 * tig];
            uint2 v1 = *(const uint2*)&Zs[(ra + 8) * PITCH + ks * 8 + 2 * tig];
            a[mt][0] = v0.x; a[mt][2] = v0.y; a[mt][1] = v1.x; a[mt][3] = v1.y;
        }
#pragma unroll
        for (int nt = 0; nt < 8; nt++) {
            int nb = warp_n * 64 + nt * 8 + gid;
            uint2 v = *(const uint2*)&Ws[nb * PITCH + ks * 8 + 2 * tig];
            b[nt][0] = v.x; b[nt][1] = v.y;
        }
#pragma unroll
        for (int mt = 0; mt < 2; mt++)
#pragma unroll
            for (int nt = 0; nt < 8; nt++) mma_tf32(c[mt][nt], a[mt], b[nt]);
    }
    __syncthreads();   // all warps done reading Zs/Ws

    // epilogue1: t = relu(C + b1) -> Zs (tf32 bits, permuted cols)
#pragma unroll
    for (int mt = 0; mt < 2; mt++) {
#pragma unroll
        for (int nt = 0; nt < 8; nt++) {
            int rowl = warp_m * 32 + mt * 16 + gid;
            int colg = warp_n * 64 + nt * 8;
            int col = colg + 2 * tig;
            float bb0 = sb1[col], bb1 = sb1[col + 1];
            Zs[rowl * PITCH + colg + p0] = __uint_as_float(f2tf32(fmaxf(c[mt][nt][0] + bb0, 0.f)));
            Zs[rowl * PITCH + colg + p1] = __uint_as_float(f2tf32(fmaxf(c[mt][nt][1] + bb1, 0.f)));
            Zs[(rowl + 8) * PITCH + colg + p0] = __uint_as_float(f2tf32(fmaxf(c[mt][nt][2] + bb0, 0.f)));
            Zs[(rowl + 8) * PITCH + colg + p1] = __uint_as_float(f2tf32(fmaxf(c[mt][nt][3] + bb1, 0.f)));
#pragma unroll
            for (int i = 0; i < 4; i++) c[mt][nt][i] = 0.f;
        }
    }
    // stage W2^T
    {
        const uint4* wg = (const uint4*)WT2;
#pragma unroll
        for (int i = 0; i < 16; i++) {
            int idx = i * 256 + tid;
            int row = idx >> 5, c4 = idx & 31;
            *(uint4*)&Ws[row * PITCH + c4 * 4] = __ldg(&wg[idx]);
        }
    }
    __syncthreads();

    // GEMM2
#pragma unroll
    for (int ks = 0; ks < 16; ks++) {
        uint32_t a[2][4], b[8][2];
#pragma unroll
        for (int mt = 0; mt < 2; mt++) {
            int ra = warp_m * 32 + mt * 16 + gid;
            uint2 v0 = *(const uint2*)&Zs[ra * PITCH + ks * 8 + 2 * tig];
            uint2 v1 = *(const uint2*)&Zs[(ra + 8) * PITCH + ks * 8 + 2 * tig];
            a[mt][0] = v0.x; a[mt][2] = v0.y; a[mt][1] = v1.x; a[mt][3] = v1.y;
        }
#pragma unroll
        for (int nt = 0; nt < 8; nt++) {
            int nb = warp_n * 64 + nt * 8 + gid;
            uint2 v = *(const uint2*)&Ws[nb * PITCH + ks * 8 + 2 * tig];
            b[nt][0] = v.x; b[nt][1] = v.y;
        }
#pragma unroll
        for (int mt = 0; mt < 2; mt++)
#pragma unroll
            for (int nt = 0; nt < 8; nt++) mma_tf32(c[mt][nt], a[mt], b[nt]);
    }

    // epilogue2: h += relu(C*sc0 + sc1), guarded RMW
#pragma unroll
    for (int mt = 0; mt < 2; mt++) {
#pragma unroll
        for (int nt = 0; nt < 8; nt++) {
            int rowl = warp_m * 32 + mt * 16 + gid;
            int col = warp_n * 64 + nt * 8 + 2 * tig;
            float s0 = sc0[col], s1 = sc0[col + 1];
            float k0 = sc1[col], k1 = sc1[col + 1];
            int gr0 = rbase + rowl, gr1 = gr0 + 8;
            if (gr0 < NN) {
                float2 hv = *(float2*)&g_h[(size_t)gr0 * HID + col];
                hv.x += fmaxf(c[mt][nt][0] * s0 + k0, 0.f);
                hv.y += fmaxf(c[mt][nt][1] * s1 + k1, 0.f);
                *(float2*)&g_h[(size_t)gr0 * HID + col] = hv;
            }
            if (gr1 < NN) {
                float2 hv = *(float2*)&g_h[(size_t)gr1 * HID + col];
                hv.x += fmaxf(c[mt][nt][2] * s0 + k0, 0.f);
                hv.y += fmaxf(c[mt][nt][3] * s1 + k1, 0.f);
                *(float2*)&g_h[(size_t)gr1 * HID + col] = hv;
            }
        }
    }
}

// ---------------- pooling ----------------
__global__ void pool_kernel(const int* __restrict__ batch) {
    int wid = (blockIdx.x * blockDim.x + threadIdx.x) >> 5;
    if (wid >= NN) return;
    int lane = threadIdx.x & 31;
    int g = __ldg(&batch[wid]);
    float4 hv = ((const float4*)g_h)[wid * 32 + lane];
    float* sp = &g_sums[g * HID + lane * 4];
    atomicAdd(sp + 0, hv.x);
    atomicAdd(sp + 1, hv.y);
    atomicAdd(sp + 2, hv.z);
    atomicAdd(sp + 3, hv.w);
    if (lane == 0) atomicAdd(&g_gcnt[g], 1);
}

__global__ void final_kernel(const float* __restrict__ mlp_w, const float* __restrict__ mlp_b,
                             float* __restrict__ out) {
    int g = (blockIdx.x * blockDim.x + threadIdx.x) >> 5;
    if (g >= NG) return;
    int lane = threadIdx.x & 31;
    float cnt = fmaxf((float)g_gcnt[g], 1.f);
    float4 sv = ((const float4*)g_sums)[g * 32 + lane];
    float4 wv = ((const float4*)mlp_w)[lane];
    float p = (sv.x * wv.x + sv.y * wv.y + sv.z * wv.z + sv.w * wv.w) / cnt;
#pragma unroll
    for (int off = 16; off; off >>= 1) p += __shfl_xor_sync(0xFFFFFFFFu, p, off);
    if (lane == 0) out[g] = p + __ldg(&mlp_b[0]);
}

extern "C" void kernel_launch(void* const* d_in, const int* in_sizes, int n_in,
                              void* d_out, int out_size) {
    const int*   x        = (const int*)d_in[0];
    const int*   ei       = (const int*)d_in[1];
    const int*   ea       = (const int*)d_in[2];
    const int*   batch    = (const int*)d_in[3];
    const float* atom_emb = (const float*)d_in[4];
    const float* bond_emb = (const float*)d_in[5];
    const float* l1w      = (const float*)d_in[6];
    const float* l1b      = (const float*)d_in[7];
    const float* l2w      = (const float*)d_in[8];
    const float* l2b      = (const float*)d_in[9];
    const float* gam      = (const float*)d_in[10];
    const float* bet      = (const float*)d_in[11];
    const float* bnm      = (const float*)d_in[12];
    const float* bnv      = (const float*)d_in[13];
    const float* mlw      = (const float*)d_in[14];
    const float* mlb      = (const float*)d_in[15];
    float* out = (float*)d_out;

    cudaFuncSetAttribute(mlp_mma_kernel, cudaFuncAttributeMaxDynamicSharedMemorySize, SMEM_MMA);

    zero_kernel<<<(NN + 255) / 256, 256>>>();
    hist_kernel<<<(NE + 255) / 256, 256>>>(ei);
    scan_kernel<<<1, 1024>>>();
    scatter_kernel<<<(NE + 255) / 256, 256>>>(ei, ea);
    wtrans_kernel<<<dim3(4, 4, 8), dim3(32, 8)>>>(l1w, l2w);
    embed_kernel<<<NN / 8, 256>>>(x, atom_emb);

    for (int l = 0; l < NUM_L; l++) {
        agg_kernel<<<NN / 8, 256>>>(bond_emb);
        mlp_mma_kernel<<<NTILES, 256, SMEM_MMA>>>(
            l, l1b + l * HID, l2b + l * HID,
            gam + l * HID, bet + l * HID, bnm + l * HID, bnv + l * HID);
    }

    pool_kernel<<<NN / 8, 256>>>(batch);
    final_kernel<<<NG / 8, 256>>>(mlw, mlb, out);
}